// round 13
// baseline (speedup 1.0000x reference)
#include <cuda_runtime.h>
#include <cuda_bf16.h>
#include <math.h>

#define H 512
#define W 512
#define HW (H*W)
#define CH 32
#define CHW (CH*HW)
#define OD2 518
#define S2 (OD2*OD2)
#define ICB 4

__device__ float g_t1[CHW];
__device__ float g_t1n[CHW];
__device__ float g_t2[CHW];
__device__ float g_gates[4*CHW];
__device__ float g_r1[CHW];
__device__ float g_r2[3*S2];
__device__ __align__(16) unsigned int   g_xp[64*HW];            // (hi,lo) packed concat input
__device__ __align__(16) unsigned short g_wpB[4*9*2*32*136];    // B tiles [g][tap][var][n][136]
__device__ double g_sum[8*32];
__device__ double g_sq[8*32];
__device__ float g_mean[8*32];
__device__ float g_rs[8*32];

// ---- f32x2 helpers ----
__device__ __forceinline__ unsigned long long dup2(float v) {
    unsigned long long d; asm("mov.b64 %0, {%1, %1};" : "=l"(d) : "f"(v)); return d;
}
__device__ __forceinline__ unsigned long long pk2(float lo, float hi) {
    unsigned long long d; asm("mov.b64 %0, {%1, %2};" : "=l"(d) : "f"(lo), "f"(hi)); return d;
}
__device__ __forceinline__ void fma2(unsigned long long& d,
                                     unsigned long long a, unsigned long long b) {
    asm("fma.rn.f32x2 %0, %1, %2, %0;" : "+l"(d) : "l"(a), "l"(b));
}
__device__ __forceinline__ float2 unpack2(unsigned long long d) {
    float2 f; asm("mov.b64 {%0, %1}, %2;" : "=f"(f.x), "=f"(f.y) : "l"(d)); return f;
}

// ---- cp.async ----
__device__ __forceinline__ void cp4(unsigned int dst, const void* src, bool pred) {
    int sz = pred ? 4 : 0;
    asm volatile("cp.async.ca.shared.global [%0], [%1], 4, %2;\n" :: "r"(dst), "l"(src), "r"(sz));
}
__device__ __forceinline__ void cp_commit() { asm volatile("cp.async.commit_group;"); }
template<int N> __device__ __forceinline__ void cp_wait() {
    asm volatile("cp.async.wait_group %0;" :: "n"(N));
}

// ---- mma / ldmatrix (baseline PTX, valid on sm_103 plain) ----
__device__ __forceinline__ unsigned int smem_to_u32(const void* p) {
    unsigned int a;
    asm("{ .reg .u64 t; cvta.to.shared.u64 t, %1; cvt.u32.u64 %0, t; }" : "=r"(a) : "l"(p));
    return a;
}
#define LDSM4(r0,r1,r2,r3,addr) \
    asm volatile("ldmatrix.sync.aligned.m8n8.x4.shared.b16 {%0,%1,%2,%3}, [%4];" \
        : "=r"(r0),"=r"(r1),"=r"(r2),"=r"(r3) : "r"(addr))
#define LDSM2(r0,r1,addr) \
    asm volatile("ldmatrix.sync.aligned.m8n8.x2.shared.b16 {%0,%1}, [%2];" \
        : "=r"(r0),"=r"(r1) : "r"(addr))
#define MMA16816(c,a0,a1,a2,a3,b0,b1) \
    asm volatile("mma.sync.aligned.m16n8k16.row.col.f32.bf16.bf16.f32 " \
        "{%0,%1,%2,%3}, {%4,%5,%6,%7}, {%8,%9}, {%0,%1,%2,%3};" \
        : "+f"((c)[0]),"+f"((c)[1]),"+f"((c)[2]),"+f"((c)[3]) \
        : "r"(a0),"r"(a1),"r"(a2),"r"(a3),"r"(b0),"r"(b1))

// ---- small kernels ----
__global__ void zero_stats() { int i = threadIdx.x; g_sum[i] = 0.0; g_sq[i] = 0.0; }

__global__ void finalize_stats(int sb, int nch, double invN) {
    int st = sb + blockIdx.x, t = threadIdx.x;
    if (t < nch) {
        int idx = st*32 + t;
        double m = g_sum[idx]*invN, var = g_sq[idx]*invN - m*m;
        g_mean[idx] = (float)m;
        g_rs[idx] = (float)(1.0 / sqrt(var + 1e-5));
    }
}

template<int RELU>
__global__ void __launch_bounds__(256)
normalize(const float* __restrict__ in, float* __restrict__ out, int stage)
{
    long i4 = (long)blockIdx.x*256 + threadIdx.x;
    if (i4 >= CHW/4) return;
    int c = (int)(i4 >> 16);
    float m = g_mean[stage*32 + c], rs = g_rs[stage*32 + c];
    float4 v = ((const float4*)in)[i4];
    v.x = (v.x - m)*rs; v.y = (v.y - m)*rs; v.z = (v.z - m)*rs; v.w = (v.w - m)*rs;
    if (RELU) {
        v.x = v.x > 0.f ? v.x : 0.f; v.y = v.y > 0.f ? v.y : 0.f;
        v.z = v.z > 0.f ? v.z : 0.f; v.w = v.w > 0.f ? v.w : 0.f;
    }
    ((float4*)out)[i4] = v;
}

// ---- hi/lo pack ----
__device__ __forceinline__ unsigned int packhl(float vv) {
    __nv_bfloat16 hb = __float2bfloat16(vv);
    __nv_bfloat16 lb = __float2bfloat16(vv - __bfloat162float(hb));
    return (unsigned int)__bfloat16_as_ushort(hb) | ((unsigned int)__bfloat16_as_ushort(lb) << 16);
}
__global__ void __launch_bounds__(256)
pack_raw4(const float* __restrict__ src, unsigned int* __restrict__ dst)
{
    long i4 = (long)blockIdx.x*256 + threadIdx.x;
    if (i4 >= CHW/4) return;
    float4 v = ((const float4*)src)[i4];
    ((uint4*)dst)[i4] = make_uint4(packhl(v.x), packhl(v.y), packhl(v.z), packhl(v.w));
}
__global__ void __launch_bounds__(256)
pack_bn4(const float* __restrict__ src, unsigned int* __restrict__ dst, int stage)
{
    long i4 = (long)blockIdx.x*256 + threadIdx.x;
    if (i4 >= CHW/4) return;
    int c = (int)(i4 >> 16);
    float m = g_mean[stage*32 + c], rs = g_rs[stage*32 + c];
    float4 v = ((const float4*)src)[i4];
    ((uint4*)dst)[i4] = make_uint4(packhl((v.x - m)*rs), packhl((v.y - m)*rs),
                                   packhl((v.z - m)*rs), packhl((v.w - m)*rs));
}

// ---- weight pack: B' tiles [g][tap][var][n=32][k=136 padded] bf16 ----
// k = 2*ic + p. var0: whi for both p; var1: p0 = wlo, p1 = 0.
__global__ void wpack(const float* __restrict__ w0, const float* __restrict__ w1,
                      const float* __restrict__ w2, const float* __restrict__ w3,
                      unsigned short* __restrict__ dst)
{
    const int tap = blockIdx.x, v = blockIdx.y, g = blockIdx.z;
    const float* ws = (g==0)?w0:(g==1)?w1:(g==2)?w2:w3;
    unsigned short* tile = dst + (long)(((g*9 + tap)*2 + v)*32)*136;
    for (int e = threadIdx.x; e < 32*128; e += blockDim.x) {
        int n = e >> 7, k = e & 127;
        int ic = k >> 1, p = k & 1;
        float w = ws[((long)n*64 + ic)*9 + tap];
        __nv_bfloat16 whi = __float2bfloat16(w), val;
        if (v == 0) val = whi;
        else if (p == 0) val = __float2bfloat16(w - __bfloat162float(whi));
        else val = __float2bfloat16(0.f);
        tile[n*136 + k] = __bfloat16_as_ushort(val);
    }
}

// ---- tensor-core gates conv via mma.sync: block = 1 gate, 64px x 64 rows ----
#define AROWB 272               // bytes per A pixel-row (136 bf16)
#define ABYTES (66*AROWB)       // 17952 per ring slot
#define BTB (32*AROWB)          // 8704 per B tile
__global__ void __launch_bounds__(256, 1)
tcgates(const unsigned int* __restrict__ xp, const unsigned short* __restrict__ wpB,
        float* __restrict__ gates,
        double* __restrict__ o_sum, double* __restrict__ o_sq)
{
    extern __shared__ unsigned char sm[];
    unsigned short* sB = (unsigned short*)sm;              // 18 tiles = 156672 B
    unsigned char*  sA = sm + 18*BTB;                      // 4 ring slots = 71808 B
    __shared__ float s_stats[64];

    const int tid = threadIdx.x, wid = tid >> 5, lane = tid & 31;
    const int strip = wid >> 1, nhalf = wid & 1;
    const int x0 = blockIdx.x*64, ys = blockIdx.y*64, g = blockIdx.z;

    // load this gate's B tiles (once)
    {
        const float4* bs = (const float4*)(wpB + (long)g*9*2*32*136);
        float4* bd = (float4*)sB;
        for (int i = tid; i < 18*32*17; i += 256) bd[i] = bs[i];
    }
    if (tid < 64) s_stats[tid] = 0.f;

    const unsigned int sAu = smem_to_u32(sA);
    const unsigned int sBu = smem_to_u32(sB);

    // A row loader: row y -> ring slot (y+4)&3 ; 66 px window [x0-1, x0+64]
    auto issueA = [&](int y) {
        unsigned int base = sAu + (unsigned int)(((y + 4) & 3) * ABYTES);
        for (int e = tid; e < 66*64; e += 256) {
            int ic = e & 63, p = e >> 6;
            int px = x0 - 1 + p;
            bool ok = (y >= 0) && (y < H) && (px >= 0) && (px < W);
            const unsigned int* src = ok ? (xp + (long)ic*HW + (long)y*W + px) : xp;
            cp4(base + (unsigned int)(p*AROWB + ic*4), src, ok);
        }
        cp_commit();
    };

    issueA(ys - 1); issueA(ys); issueA(ys + 1);
    __syncthreads();                 // B visible; cp groups handled by waits below

    float sacc[2][2] = {{0.f,0.f},{0.f,0.f}}, qacc[2][2] = {{0.f,0.f},{0.f,0.f}};
    const int mbase = strip*16;
    const unsigned int a_lane_off =
        (unsigned int)((lane & 15)*AROWB + ((lane >> 4)*16));
    const unsigned int b_lane_off =
        (unsigned int)((lane & 7)*AROWB + (((lane >> 3) & 1)*16));

    for (int y = ys; y < ys + 64; y++) {
        issueA(y + 2);
        cp_wait<1>();
        __syncthreads();

        float c[2][4];
#pragma unroll
        for (int nt = 0; nt < 2; nt++)
#pragma unroll
            for (int j = 0; j < 4; j++) c[nt][j] = 0.f;

#pragma unroll
        for (int tap = 0; tap < 9; tap++) {
            const int dy = tap/3 - 1, dx = tap - (tap/3)*3 - 1;
            const unsigned int arow = sAu + (unsigned int)(((y + dy + 4) & 3)*ABYTES);
            const unsigned int abase = arow + (unsigned int)((mbase + dx + 1)*AROWB) + a_lane_off;
            const unsigned int bt0 = sBu + (unsigned int)((tap*2)*BTB);
#pragma unroll
            for (int ch = 0; ch < 8; ch++) {
                unsigned int a0, a1, a2, a3;
                LDSM4(a0, a1, a2, a3, abase + (unsigned int)(ch*32));
#pragma unroll
                for (int v = 0; v < 2; v++) {
                    const unsigned int bt = bt0 + (unsigned int)(v*BTB);
#pragma unroll
                    for (int nt = 0; nt < 2; nt++) {
                        unsigned int baddr = bt
                            + (unsigned int)((nhalf*16 + nt*8)*AROWB)
                            + b_lane_off + (unsigned int)(ch*32);
                        unsigned int b0, b1;
                        LDSM2(b0, b1, baddr);
                        MMA16816(c[nt], a0, a1, a2, a3, b0, b1);
                    }
                }
            }
        }

        // store + stats
        float* og = gates + (long)g*CHW + (long)y*W + x0;
        const int prow = mbase + (lane >> 2);
#pragma unroll
        for (int nt = 0; nt < 2; nt++) {
            const int oc0 = nhalf*16 + nt*8 + 2*(lane & 3);
            og[(long)oc0*HW + prow]           = c[nt][0];
            og[(long)(oc0 + 1)*HW + prow]     = c[nt][1];
            og[(long)oc0*HW + prow + 8]       = c[nt][2];
            og[(long)(oc0 + 1)*HW + prow + 8] = c[nt][3];
            sacc[nt][0] += c[nt][0] + c[nt][2];
            sacc[nt][1] += c[nt][1] + c[nt][3];
            qacc[nt][0] += c[nt][0]*c[nt][0] + c[nt][2]*c[nt][2];
            qacc[nt][1] += c[nt][1]*c[nt][1] + c[nt][3]*c[nt][3];
        }
        __syncthreads();             // protect ring slot reuse next iter
    }

#pragma unroll
    for (int nt = 0; nt < 2; nt++)
#pragma unroll
        for (int j = 0; j < 2; j++) {
            int oc = nhalf*16 + nt*8 + 2*(lane & 3) + j;
            atomicAdd(&s_stats[oc], sacc[nt][j]);
            atomicAdd(&s_stats[32 + oc], qacc[nt][j]);
        }
    __syncthreads();
    if (tid < 32) {
        atomicAdd(&o_sum[g*32 + tid], (double)s_stats[tid]);
        atomicAdd(&o_sq[g*32 + tid], (double)s_stats[32 + tid]);
    }
}

// ---- FFMA2 conv3x3 double-buffered (e1, e2, r1) ----
template<int CIN, int SPLIT>
__global__ void __launch_bounds__(256, 2)
conv2(const float* __restrict__ in, const float* __restrict__ in2,
      const float* __restrict__ w0_, const float* __restrict__ w1_,
      const float* __restrict__ w2_, const float* __restrict__ w3_,
      float* __restrict__ out, long outStrideZ,
      double* __restrict__ o_sum, double* __restrict__ o_sq)
{
    constexpr int NCH = CIN / ICB;
    constexpr int NIN = ICB*18*66;
    constexpr int NWT = ICB*9*16;
    constexpr int NTOT = NIN + NWT;

    const int z = blockIdx.z;
    const int gate = z >> 1;
    const int ocbase = (z & 1) * 16;
    const float* wt = (gate == 0) ? w0_ : (gate == 1) ? w1_ : (gate == 2) ? w2_ : w3_;
    out   += (long)gate * outStrideZ;
    o_sum += gate*32 + ocbase;
    o_sq  += gate*32 + ocbase;

    __shared__ float s_in[2][ICB][18][68];
    __shared__ float s_w[2][ICB][9][16];
    __shared__ float s_red[8][16][2];

    const int tid = threadIdx.x;
    const int tx = tid & 15, ty = tid >> 4;
    const int x0 = blockIdx.x*64 + tx*4;
    const int oy = blockIdx.y*16 + ty;
    const int gx0 = blockIdx.x*64 - 1;
    const int gy0 = blockIdx.y*16 - 1;

    unsigned long long acc[4][8];
#pragma unroll
    for (int p = 0; p < 4; p++)
#pragma unroll
        for (int q = 0; q < 8; q++) acc[p][q] = 0ULL;

    auto issue = [&](int ch, int b) {
        int ic0 = ch * ICB;
        for (int e = tid; e < NTOT; e += 256) {
            if (e < NIN) {
                int ic = e / (18*66);
                int r  = e - ic*(18*66);
                int ly = r / 66, lx = r - ly*66;
                int gy = gy0 + ly, gx = gx0 + lx;
                bool ok = (unsigned)gy < (unsigned)H && (unsigned)gx < (unsigned)W;
                int c = ic0 + ic;
                const float* src;
                if (SPLIT && c < 32) src = ok ? &in2[(long)c*HW + gy*W + gx] : in2;
                else {
                    int cc = SPLIT ? c - 32 : c;
                    src = ok ? &in[(long)cc*HW + gy*W + gx] : in;
                }
                cp4((unsigned int)__cvta_generic_to_shared(&s_in[b][ic][ly][lx]), src, ok);
            } else {
                int r = e - NIN;
                int ic = r / 144;
                int r2 = r - ic*144;
                int k = r2 >> 4, oco = r2 & 15;
                cp4((unsigned int)__cvta_generic_to_shared(&s_w[b][ic][k][oco]),
                    &wt[((long)(ocbase + oco)*CIN + ic0 + ic)*9 + k], true);
            }
        }
        cp_commit();
    };

    issue(0, 0);

    for (int n = 0; n < NCH; n++) {
        const int b = n & 1;
        if (n + 1 < NCH) { issue(n + 1, (n + 1) & 1); cp_wait<1>(); }
        else cp_wait<0>();
        __syncthreads();

#pragma unroll
        for (int i = 0; i < ICB; i++) {
#pragma unroll
            for (int r = 0; r < 3; r++) {
                float4 va = *(const float4*)&s_in[b][i][ty + r][tx*4];
                float2 vb = *(const float2*)&s_in[b][i][ty + r][tx*4 + 4];
                unsigned long long d[6] = { dup2(va.x), dup2(va.y), dup2(va.z),
                                            dup2(va.w), dup2(vb.x), dup2(vb.y) };
#pragma unroll
                for (int c = 0; c < 3; c++) {
                    const ulonglong2* wr = (const ulonglong2*)&s_w[b][i][r*3 + c][0];
                    ulonglong2 wa = wr[0], wb2 = wr[1], wc = wr[2], wd = wr[3];
                    unsigned long long wv[8] = { wa.x, wa.y, wb2.x, wb2.y,
                                                 wc.x, wc.y, wd.x, wd.y };
#pragma unroll
                    for (int p = 0; p < 4; p++)
#pragma unroll
                        for (int q = 0; q < 8; q++)
                            fma2(acc[p][q], d[c + p], wv[q]);
                }
            }
        }
        __syncthreads();
    }

    const int lane = tid & 31, wid = tid >> 5;
    const long obase = (long)oy*W + x0;
#pragma unroll
    for (int q = 0; q < 8; q++) {
        float2 v0 = unpack2(acc[0][q]), v1 = unpack2(acc[1][q]);
        float2 v2 = unpack2(acc[2][q]), v3 = unpack2(acc[3][q]);
        float4 lo = make_float4(v0.x, v1.x, v2.x, v3.x);
        float4 hi = make_float4(v0.y, v1.y, v2.y, v3.y);
        *(float4*)(out + (long)(ocbase + 2*q    )*HW + obase) = lo;
        *(float4*)(out + (long)(ocbase + 2*q + 1)*HW + obase) = hi;

        float sl = lo.x + lo.y + lo.z + lo.w;
        float ql = lo.x*lo.x + lo.y*lo.y + lo.z*lo.z + lo.w*lo.w;
        float sh = hi.x + hi.y + hi.z + hi.w;
        float qh = hi.x*hi.x + hi.y*hi.y + hi.z*hi.z + hi.w*hi.w;
#pragma unroll
        for (int o2 = 16; o2 > 0; o2 >>= 1) {
            sl += __shfl_xor_sync(0xffffffffu, sl, o2);
            ql += __shfl_xor_sync(0xffffffffu, ql, o2);
            sh += __shfl_xor_sync(0xffffffffu, sh, o2);
            qh += __shfl_xor_sync(0xffffffffu, qh, o2);
        }
        if (lane == 0) {
            s_red[wid][2*q][0] = sl; s_red[wid][2*q][1] = ql;
            s_red[wid][2*q + 1][0] = sh; s_red[wid][2*q + 1][1] = qh;
        }
    }
    __syncthreads();
    if (tid < 16) {
        double s = 0.0, qq = 0.0;
#pragma unroll
        for (int wdx = 0; wdx < 8; wdx++) { s += (double)s_red[wdx][tid][0]; qq += (double)s_red[wdx][tid][1]; }
        atomicAdd(&o_sum[tid], s);
        atomicAdd(&o_sq[tid], qq);
    }
}

// ---- r2 conv (pad 4, 3 oc) ----
__global__ void __launch_bounds__(256, 2)
convr2(const float* __restrict__ in, const float* __restrict__ wt,
       float* __restrict__ outg, double* __restrict__ o_sum, double* __restrict__ o_sq)
{
    constexpr int NCH = 8;
    constexpr int NIN = ICB*18*66;
    __shared__ float s_in[2][ICB][18][68];
    __shared__ float s_wr[32][9][4];
    __shared__ float s_red[8][3][2];

    const int tid = threadIdx.x;
    const int tx = tid & 15, ty = tid >> 4;
    const int x0 = blockIdx.x*64;
    const int oy = blockIdx.y*16 + ty;
    const int gx0 = x0 - 4, gy0 = blockIdx.y*16 - 4;

    unsigned long long acc[2][3];
#pragma unroll
    for (int p = 0; p < 2; p++)
#pragma unroll
        for (int q = 0; q < 3; q++) acc[p][q] = 0ULL;

    auto issue = [&](int ch, int b) {
        const int ic0 = ch * ICB;
        for (int e = tid; e < NIN; e += 256) {
            int ic = e / (18*66);
            int r = e - ic*(18*66);
            int ly = r / 66, lx = r - ly*66;
            int gy = gy0 + ly, gx = gx0 + lx;
            bool ok = (unsigned)gy < (unsigned)H && (unsigned)gx < (unsigned)W;
            const float* src = ok ? &in[(long)(ic0 + ic)*HW + gy*W + gx] : in;
            cp4((unsigned int)__cvta_generic_to_shared(&s_in[b][ic][ly][lx]), src, ok);
        }
        cp_commit();
    };

    issue(0, 0);
    for (int e = tid; e < 32*9*3; e += 256) {
        int ic = e / 27, r = e - ic*27, k = r / 3, oc = r - k*3;
        s_wr[ic][k][oc] = wt[((long)oc*32 + ic)*9 + k];
    }

    for (int n = 0; n < NCH; n++) {
        const int b = n & 1;
        if (n + 1 < NCH) { issue(n + 1, (n + 1) & 1); cp_wait<1>(); }
        else cp_wait<0>();
        __syncthreads();
#pragma unroll
        for (int i = 0; i < ICB; i++) {
            const float* wbase = &s_wr[n*ICB + i][0][0];
#pragma unroll
            for (int r = 0; r < 3; r++) {
                const float* ip = &s_in[b][i][ty + r][tx*4];
                float4 va = *(const float4*)ip;
                float2 vb = *(const float2*)(ip + 4);
                unsigned long long q01 = pk2(va.x, va.y), q12 = pk2(va.y, va.z);
                unsigned long long q23 = pk2(va.z, va.w), q34 = pk2(va.w, vb.x);
                unsigned long long q45 = pk2(vb.x, vb.y);
                unsigned long long pr[3][2] = { {q01, q23}, {q12, q34}, {q23, q45} };
#pragma unroll
                for (int c = 0; c < 3; c++) {
                    float4 w4 = *(const float4*)(wbase + (r*3 + c)*4);
                    unsigned long long w0 = dup2(w4.x), w1 = dup2(w4.y), w2 = dup2(w4.z);
                    fma2(acc[0][0], pr[c][0], w0); fma2(acc[1][0], pr[c][1], w0);
                    fma2(acc[0][1], pr[c][0], w1); fma2(acc[1][1], pr[c][1], w1);
                    fma2(acc[0][2], pr[c][0], w2); fma2(acc[1][2], pr[c][1], w2);
                }
            }
        }
        __syncthreads();
    }

    const int lane = tid & 31, wid = tid >> 5;
#pragma unroll
    for (int oc = 0; oc < 3; oc++) {
        float2 u0 = unpack2(acc[0][oc]), u1 = unpack2(acc[1][oc]);
        float v[4] = { u0.x, u0.y, u1.x, u1.y };
        float s = 0.f, q = 0.f;
#pragma unroll
        for (int j = 0; j < 4; j++) {
            int ox = x0 + tx*4 + j;
            bool ok = (ox < OD2) && (oy < OD2);
            float t = ok ? v[j] : 0.f;
            if (ok) outg[(long)oc*S2 + (long)oy*OD2 + ox] = t;
            s += t; q += t*t;
        }
#pragma unroll
        for (int o2 = 16; o2 > 0; o2 >>= 1) {
            s += __shfl_xor_sync(0xffffffffu, s, o2);
            q += __shfl_xor_sync(0xffffffffu, q, o2);
        }
        if (lane == 0) { s_red[wid][oc][0] = s; s_red[wid][oc][1] = q; }
    }
    __syncthreads();
    if (tid < 3) {
        double s = 0.0, qq = 0.0;
#pragma unroll
        for (int wdx = 0; wdx < 8; wdx++) { s += (double)s_red[wdx][tid][0]; qq += (double)s_red[wdx][tid][1]; }
        atomicAdd(&o_sum[tid], s);
        atomicAdd(&o_sq[tid], qq);
    }
}

// ---- LSTM elementwise ----
__device__ __forceinline__ float fsig(float x) { return __fdividef(1.f, 1.f + __expf(-x)); }
__device__ __forceinline__ float ftanh(float x) {
    float e = __expf(-2.f*x); return __fdividef(1.f - e, 1.f + e);
}
__global__ void lstm_elem(const float* __restrict__ prev_c, float* __restrict__ out)
{
    long i4 = (long)blockIdx.x*256 + threadIdx.x;
    if (i4 >= CHW/4) return;
    int c = (int)(i4 >> 16);
    float mf = g_mean[64 + c], rf = g_rs[64 + c];
    float mi = g_mean[96 + c], ri = g_rs[96 + c];
    float mc = g_mean[128 + c], rc = g_rs[128 + c];
    float mo = g_mean[160 + c], ro = g_rs[160 + c];
    float4 gf = ((const float4*)g_gates)[i4];
    float4 gi = ((const float4*)(g_gates + CHW))[i4];
    float4 gc = ((const float4*)(g_gates + 2L*CHW))[i4];
    float4 go = ((const float4*)(g_gates + 3L*CHW))[i4];
    float4 pc = ((const float4*)prev_c)[i4];
    float4 ncv, nhv;
#define LSTM1(X) { \
        float f = fsig((gf.X - mf)*rf), it = fsig((gi.X - mi)*ri); \
        float ct = ftanh((gc.X - mc)*rc), ot = fsig((go.X - mo)*ro); \
        ncv.X = pc.X*f + it*ct; nhv.X = ftanh(ncv.X)*ot; }
    LSTM1(x) LSTM1(y) LSTM1(z) LSTM1(w)
#undef LSTM1
    ((float4*)out)[i4] = ncv;
    ((float4*)(out + CHW))[i4] = nhv;
}

// ---- gather ----
__global__ void gather_k(const int* __restrict__ coords,
                         const float* __restrict__ w_oil, const float* __restrict__ b_oil,
                         const float* __restrict__ w_wat, const float* __restrict__ b_wat,
                         const float* __restrict__ w_gas, const float* __restrict__ b_gas,
                         float* __restrict__ out)
{
    int i = threadIdx.x;
    if (i >= 256) return;
    int row = coords[2*i] + 3, col = coords[2*i + 1] + 3;
    float wv[3] = { w_oil[0], w_wat[0], w_gas[0] };
    float bv[3] = { b_oil[0], b_wat[0], b_gas[0] };
#pragma unroll
    for (int ch = 0; ch < 3; ch++) {
        float v = (g_r2[(long)ch*S2 + (long)row*OD2 + col] - g_mean[224 + ch]) * g_rs[224 + ch];
        out[2L*CHW + (long)i*3 + ch] = v * wv[ch] + bv[ch];
    }
}

// ---- launch ----
extern "C" void kernel_launch(void* const* d_in, const int* in_sizes, int n_in,
                              void* d_out, int out_size)
{
    const float* x      = (const float*)d_in[0];
    const float* prev_c = (const float*)d_in[1];
    const float* prev_h = (const float*)d_in[2];
    const int*   holes  = (const int*)  d_in[3];
    const float* w_e1 = (const float*)d_in[4];
    const float* w_e2 = (const float*)d_in[5];
    const float* w_f  = (const float*)d_in[6];
    const float* w_i  = (const float*)d_in[7];
    const float* w_c  = (const float*)d_in[8];
    const float* w_o  = (const float*)d_in[9];
    const float* w_r1 = (const float*)d_in[10];
    const float* w_r2 = (const float*)d_in[11];
    const float* w_oil = (const float*)d_in[12];
    const float* b_oil = (const float*)d_in[13];
    const float* w_wat = (const float*)d_in[14];
    const float* b_wat = (const float*)d_in[15];
    const float* w_gas = (const float*)d_in[16];
    const float* b_gas = (const float*)d_in[17];
    float* out = (float*)d_out;

    float *t1, *t1n, *t2, *gates, *r1, *r2;
    unsigned int* xp; unsigned short* wpB;
    double *sum, *sq;
    cudaGetSymbolAddress((void**)&t1, g_t1);
    cudaGetSymbolAddress((void**)&t1n, g_t1n);
    cudaGetSymbolAddress((void**)&t2, g_t2);
    cudaGetSymbolAddress((void**)&gates, g_gates);
    cudaGetSymbolAddress((void**)&r1, g_r1);
    cudaGetSymbolAddress((void**)&r2, g_r2);
    cudaGetSymbolAddress((void**)&xp, g_xp);
    cudaGetSymbolAddress((void**)&wpB, g_wpB);
    cudaGetSymbolAddress((void**)&sum, g_sum);
    cudaGetSymbolAddress((void**)&sq, g_sq);

    const double invHW = 1.0 / (double)HW;
    const double invS2 = 1.0 / (double)S2;
    const int SMB = 18*BTB + 4*ABYTES;       // 156672 + 71808 = 228480
    cudaFuncSetAttribute(tcgates, cudaFuncAttributeMaxDynamicSharedMemorySize, SMB);

    dim3 blk(256);
    dim3 gw2(8, 32, 2);
    dim3 gr2(9, 33, 1);
    dim3 gtc(8, 8, 4);
    const int NB4 = (CHW/4 + 255) / 256;

    zero_stats<<<1, 256>>>();
    wpack<<<dim3(9, 2, 4), 128>>>(w_f, w_i, w_c, w_o, wpB);
    pack_raw4<<<NB4, 256>>>(prev_h, xp);                      // concat ch 0..31 = prev_h

    conv2<4, 0><<<gw2, blk>>>(x, nullptr, w_e1, w_e1, w_e1, w_e1, t1, 0, sum + 0, sq + 0);
    finalize_stats<<<1, 32>>>(0, 32, invHW);
    normalize<1><<<NB4, 256>>>(t1, t1n, 0);

    conv2<32, 0><<<gw2, blk>>>(t1n, nullptr, w_e2, w_e2, w_e2, w_e2, t2, 0, sum + 32, sq + 32);
    finalize_stats<<<1, 32>>>(1, 32, invHW);
    pack_bn4<<<NB4, 256>>>(t2, xp + 32L*HW, 1);               // concat ch 32..63 = bn(t2)

    tcgates<<<gtc, blk, SMB>>>(xp, wpB, gates, sum + 64, sq + 64);
    finalize_stats<<<4, 32>>>(2, 32, invHW);

    lstm_elem<<<NB4, 256>>>(prev_c, out);

    conv2<32, 0><<<gw2, blk>>>(out + CHW, nullptr, w_r1, w_r1, w_r1, w_r1, r1, 0, sum + 192, sq + 192);
    finalize_stats<<<1, 32>>>(6, 32, invHW);
    normalize<1><<<NB4, 256>>>(r1, t1n, 6);

    convr2<<<gr2, blk>>>(t1n, w_r2, r2, sum + 224, sq + 224);
    finalize_stats<<<1, 32>>>(7, 3, invS2);

    gather_k<<<1, 256>>>(holes, w_oil, b_oil, w_wat, b_wat, w_gas, b_gas, out);
}

// round 14
// speedup vs baseline: 1.6094x; 1.6094x over previous
#include <cuda_runtime.h>
#include <cuda_bf16.h>
#include <math.h>

#define H 512
#define W 512
#define HW (H*W)
#define CH 32
#define CHW (CH*HW)
#define OD2 518
#define S2 (OD2*OD2)
#define ICB 4

__device__ float g_t1[CHW];
__device__ float g_t1n[CHW];
__device__ float g_t2[CHW];
__device__ float g_gates[4*CHW];
__device__ float g_r1[CHW];
__device__ float g_r2[3*S2];
__device__ __align__(16) unsigned short g_xa64[(long)HW*128];   // px-major A image (gates)
__device__ __align__(16) unsigned short g_xa32[(long)HW*64];    // px-major A image (e2/r1)
__device__ __align__(16) unsigned short g_wp64[4*9*2*32*136];   // gates B tiles
__device__ __align__(16) unsigned short g_wp32[2*9*2*32*72];    // e2/r1 B tiles
__device__ double g_sum[8*32];
__device__ double g_sq[8*32];
__device__ float g_mean[8*32];
__device__ float g_rs[8*32];

// ---- f32x2 helpers ----
__device__ __forceinline__ unsigned long long dup2(float v) {
    unsigned long long d; asm("mov.b64 %0, {%1, %1};" : "=l"(d) : "f"(v)); return d;
}
__device__ __forceinline__ unsigned long long pk2(float lo, float hi) {
    unsigned long long d; asm("mov.b64 %0, {%1, %2};" : "=l"(d) : "f"(lo), "f"(hi)); return d;
}
__device__ __forceinline__ void fma2(unsigned long long& d,
                                     unsigned long long a, unsigned long long b) {
    asm("fma.rn.f32x2 %0, %1, %2, %0;" : "+l"(d) : "l"(a), "l"(b));
}
__device__ __forceinline__ float2 unpack2(unsigned long long d) {
    float2 f; asm("mov.b64 {%0, %1}, %2;" : "=f"(f.x), "=f"(f.y) : "l"(d)); return f;
}

// ---- cp.async ----
__device__ __forceinline__ void cp4(unsigned int dst, const void* src, bool pred) {
    int sz = pred ? 4 : 0;
    asm volatile("cp.async.ca.shared.global [%0], [%1], 4, %2;\n" :: "r"(dst), "l"(src), "r"(sz));
}
__device__ __forceinline__ void cp16(unsigned int dst, const void* src, bool pred) {
    int sz = pred ? 16 : 0;
    asm volatile("cp.async.cg.shared.global [%0], [%1], 16, %2;\n" :: "r"(dst), "l"(src), "r"(sz));
}
__device__ __forceinline__ void cp_commit() { asm volatile("cp.async.commit_group;"); }
template<int N> __device__ __forceinline__ void cp_wait() {
    asm volatile("cp.async.wait_group %0;" :: "n"(N));
}

// ---- mma / ldmatrix ----
__device__ __forceinline__ unsigned int smem_to_u32(const void* p) {
    unsigned int a;
    asm("{ .reg .u64 t; cvta.to.shared.u64 t, %1; cvt.u32.u64 %0, t; }" : "=r"(a) : "l"(p));
    return a;
}
#define LDSM4(r0,r1,r2,r3,addr) \
    asm volatile("ldmatrix.sync.aligned.m8n8.x4.shared.b16 {%0,%1,%2,%3}, [%4];" \
        : "=r"(r0),"=r"(r1),"=r"(r2),"=r"(r3) : "r"(addr))
#define LDSM2(r0,r1,addr) \
    asm volatile("ldmatrix.sync.aligned.m8n8.x2.shared.b16 {%0,%1}, [%2];" \
        : "=r"(r0),"=r"(r1) : "r"(addr))
#define MMA16816(c,a0,a1,a2,a3,b0,b1) \
    asm volatile("mma.sync.aligned.m16n8k16.row.col.f32.bf16.bf16.f32 " \
        "{%0,%1,%2,%3}, {%4,%5,%6,%7}, {%8,%9}, {%0,%1,%2,%3};" \
        : "+f"((c)[0]),"+f"((c)[1]),"+f"((c)[2]),"+f"((c)[3]) \
        : "r"(a0),"r"(a1),"r"(a2),"r"(a3),"r"(b0),"r"(b1))

// ---- small kernels ----
__global__ void zero_stats() { int i = threadIdx.x; g_sum[i] = 0.0; g_sq[i] = 0.0; }

__global__ void finalize_stats(int sb, int nch, double invN) {
    int st = sb + blockIdx.x, t = threadIdx.x;
    if (t < nch) {
        int idx = st*32 + t;
        double m = g_sum[idx]*invN, var = g_sq[idx]*invN - m*m;
        g_mean[idx] = (float)m;
        g_rs[idx] = (float)(1.0 / sqrt(var + 1e-5));
    }
}

template<int RELU>
__global__ void __launch_bounds__(256)
normalize(const float* __restrict__ in, float* __restrict__ out, int stage)
{
    long i4 = (long)blockIdx.x*256 + threadIdx.x;
    if (i4 >= CHW/4) return;
    int c = (int)(i4 >> 16);
    float m = g_mean[stage*32 + c], rs = g_rs[stage*32 + c];
    float4 v = ((const float4*)in)[i4];
    v.x = (v.x - m)*rs; v.y = (v.y - m)*rs; v.z = (v.z - m)*rs; v.w = (v.w - m)*rs;
    if (RELU) {
        v.x = v.x > 0.f ? v.x : 0.f; v.y = v.y > 0.f ? v.y : 0.f;
        v.z = v.z > 0.f ? v.z : 0.f; v.w = v.w > 0.f ? v.w : 0.f;
    }
    ((float4*)out)[i4] = v;
}

// ---- transpose-pack: 32ch slice of f32 [ch][HW] -> px-major bf16 hi/lo blocks ----
// dst px-row = ROWB bytes = CT*4 (CT = total ch of image). hi at k=cbase+c, lo at k=CT+cbase+c.
template<int BN, int RELU, int ROWB, int CT>
__global__ void __launch_bounds__(256)
packT(const float* __restrict__ in, unsigned short* __restrict__ dst,
      int cbase, int stage)
{
    __shared__ unsigned short sh[32][33], sl[32][33];
    const int tid = threadIdx.x;
    const int x0 = blockIdx.x*32, y = blockIdx.y;
#pragma unroll
    for (int e = tid; e < 1024; e += 256) {
        int ch = e >> 5, p = e & 31;
        float v = in[(long)ch*HW + (long)y*W + x0 + p];
        if (BN) v = (v - g_mean[stage*32 + ch]) * g_rs[stage*32 + ch];
        if (RELU) v = v > 0.f ? v : 0.f;
        __nv_bfloat16 hb = __float2bfloat16(v);
        __nv_bfloat16 lb = __float2bfloat16(v - __bfloat162float(hb));
        sh[p][ch] = __bfloat16_as_ushort(hb);
        sl[p][ch] = __bfloat16_as_ushort(lb);
    }
    __syncthreads();
    {
        int p = tid >> 3, j = tid & 7;
        unsigned int h0 = (unsigned int)sh[p][4*j] | ((unsigned int)sh[p][4*j+1] << 16);
        unsigned int h1 = (unsigned int)sh[p][4*j+2] | ((unsigned int)sh[p][4*j+3] << 16);
        unsigned int l0 = (unsigned int)sl[p][4*j] | ((unsigned int)sl[p][4*j+1] << 16);
        unsigned int l1 = (unsigned int)sl[p][4*j+2] | ((unsigned int)sl[p][4*j+3] << 16);
        unsigned char* base = (unsigned char*)dst + ((long)y*W + x0 + p)*ROWB;
        *(uint2*)(base + (cbase + 4*j)*2)      = make_uint2(h0, h1);
        *(uint2*)(base + (CT + cbase + 4*j)*2) = make_uint2(l0, l1);
    }
}

// ---- weight pack (gates, CIN=64): tiles [g][tap][var][n=32][136hw], stride 272B ----
// k<64 -> ch=k ; k>=64 -> ch=k-64. var0 = whi everywhere; var1: k<64 = wlo, else 0.
__global__ void wpack64(const float* __restrict__ w0, const float* __restrict__ w1,
                        const float* __restrict__ w2, const float* __restrict__ w3,
                        unsigned short* __restrict__ dst)
{
    const int tap = blockIdx.x, v = blockIdx.y, g = blockIdx.z;
    const float* ws = (g==0)?w0:(g==1)?w1:(g==2)?w2:w3;
    unsigned short* tile = dst + (long)(((g*9 + tap)*2 + v)*32)*136;
    for (int e = threadIdx.x; e < 32*128; e += blockDim.x) {
        int n = e >> 7, k = e & 127;
        int ch = (k < 64) ? k : (k - 64);
        float w = ws[((long)n*64 + ch)*9 + tap];
        __nv_bfloat16 whi = __float2bfloat16(w), val;
        if (v == 0) val = whi;
        else if (k < 64) val = __float2bfloat16(w - __bfloat162float(whi));
        else val = __float2bfloat16(0.f);
        tile[n*136 + k] = __bfloat16_as_ushort(val);
    }
}

// ---- weight pack (e2/r1, CIN=32): tiles [conv][tap][var][n=32][72hw], stride 144B ----
__global__ void wpack32(const float* __restrict__ we2, const float* __restrict__ wr1,
                        unsigned short* __restrict__ dst)
{
    const int tap = blockIdx.x, v = blockIdx.y, z = blockIdx.z;
    const float* ws = (z == 0) ? we2 : wr1;
    unsigned short* tile = dst + (long)(((z*9 + tap)*2 + v)*32)*72;
    for (int e = threadIdx.x; e < 32*64; e += blockDim.x) {
        int n = e >> 6, k = e & 63;
        int ch = (k < 32) ? k : (k - 32);
        float w = ws[((long)n*32 + ch)*9 + tap];
        __nv_bfloat16 whi = __float2bfloat16(w), val;
        if (v == 0) val = whi;
        else if (k < 32) val = __float2bfloat16(w - __bfloat162float(whi));
        else val = __float2bfloat16(0.f);
        tile[n*72 + k] = __bfloat16_as_ushort(val);
    }
}

// ---- tensor conv3x3: block = 64px x 32 rows x (1 gate) ----
// A image px-major; K = [hi(CIN) | lo(CIN)]; var0 full K, var1 hi half only.
template<int CIN>
__global__ void __launch_bounds__(256, 1)
tcconv(const unsigned short* __restrict__ xa, const unsigned short* __restrict__ wp,
       float* __restrict__ outg, long strideG,
       double* __restrict__ o_sum, double* __restrict__ o_sq)
{
    constexpr int AROW  = (CIN == 64) ? 272 : 144;   // smem px stride (bytes)
    constexpr int GROWB = 4*CIN;                      // gmem px row bytes
    constexpr int CH16  = GROWB/16;                   // cp16 per px
    constexpr int KC0   = CIN/8;                      // var0 k-chunks
    constexpr int KC1   = KC0/2;                      // var1 k-chunks
    constexpr int BTB   = 32*AROW;                    // B tile bytes
    constexpr int ABYT  = 66*AROW;                    // A ring slot bytes

    extern __shared__ unsigned char sm[];
    unsigned char* sB = sm;                           // 18*BTB
    unsigned char* sA = sm + 18*BTB;                  // 4*ABYT
    __shared__ float s_stats[64];

    const int tid = threadIdx.x, wid = tid >> 5, lane = tid & 31;
    const int strip = wid >> 1, nhalf = wid & 1;
    const int x0 = blockIdx.x*64, ys = blockIdx.y*32, g = blockIdx.z;

    // B tiles for this conv/gate (plain LDG->STS, published by first barrier)
    {
        const float4* bs = (const float4*)(wp + (long)g*18*(BTB/2));
        float4* bd = (float4*)sB;
        for (int i = tid; i < 18*BTB/16; i += 256) bd[i] = bs[i];
    }
    if (tid < 64) s_stats[tid] = 0.f;

    const unsigned int sAu = smem_to_u32(sA);
    const unsigned int sBu = smem_to_u32(sB);
    const unsigned char* xab = (const unsigned char*)xa;

    auto issueA = [&](int y) {
        unsigned int base = sAu + (unsigned int)(((y + 4) & 3) * ABYT);
        for (int e = tid; e < 66*CH16; e += 256) {
            int px = e / CH16, c = e - px*CH16;
            int gx = x0 - 1 + px;
            bool ok = (y >= 0) && (y < H) && (gx >= 0) && (gx < W);
            const void* src = ok ? (const void*)(xab + ((long)y*W + gx)*GROWB + c*16)
                                 : (const void*)xab;
            cp16(base + (unsigned int)(px*AROW + c*16), src, ok);
        }
        cp_commit();
    };

    issueA(ys - 1); issueA(ys); issueA(ys + 1);
    __syncthreads();

    float sacc[2][2] = {{0.f,0.f},{0.f,0.f}}, qacc[2][2] = {{0.f,0.f},{0.f,0.f}};
    const int mbase = strip*16;
    const unsigned int a_lane_off =
        (unsigned int)((lane & 15)*AROW + ((lane >> 4)*16));
    const unsigned int b_lane_off =
        (unsigned int)((lane & 7)*AROW + (((lane >> 3) & 1)*16));

    for (int y = ys; y < ys + 32; y++) {
        issueA(y + 2);
        cp_wait<1>();
        __syncthreads();

        float c[2][4];
#pragma unroll
        for (int nt = 0; nt < 2; nt++)
#pragma unroll
            for (int j = 0; j < 4; j++) c[nt][j] = 0.f;

#pragma unroll
        for (int tap = 0; tap < 9; tap++) {
            const int dy = tap/3 - 1, dx = tap - (tap/3)*3 - 1;
            const unsigned int arow = sAu + (unsigned int)(((y + dy + 4) & 3)*ABYT);
            const unsigned int abase = arow + (unsigned int)((mbase + dx + 1)*AROW) + a_lane_off;
            const unsigned int bt0 = sBu + (unsigned int)((tap*2)*BTB);
            const unsigned int bt1 = bt0 + (unsigned int)BTB;
#pragma unroll
            for (int kc = 0; kc < KC0; kc++) {
                unsigned int a0, a1, a2, a3;
                LDSM4(a0, a1, a2, a3, abase + (unsigned int)(kc*32));
#pragma unroll
                for (int nt = 0; nt < 2; nt++) {
                    unsigned int baddr = bt0
                        + (unsigned int)((nhalf*16 + nt*8)*AROW)
                        + b_lane_off + (unsigned int)(kc*32);
                    unsigned int b0, b1;
                    LDSM2(b0, b1, baddr);
                    MMA16816(c[nt], a0, a1, a2, a3, b0, b1);
                }
                if (kc < KC1) {
#pragma unroll
                    for (int nt = 0; nt < 2; nt++) {
                        unsigned int baddr = bt1
                            + (unsigned int)((nhalf*16 + nt*8)*AROW)
                            + b_lane_off + (unsigned int)(kc*32);
                        unsigned int b0, b1;
                        LDSM2(b0, b1, baddr);
                        MMA16816(c[nt], a0, a1, a2, a3, b0, b1);
                    }
                }
            }
        }

        float* og = outg + (long)g*strideG + (long)y*W + x0;
        const int prow = mbase + (lane >> 2);
#pragma unroll
        for (int nt = 0; nt < 2; nt++) {
            const int oc0 = nhalf*16 + nt*8 + 2*(lane & 3);
            og[(long)oc0*HW + prow]           = c[nt][0];
            og[(long)(oc0 + 1)*HW + prow]     = c[nt][1];
            og[(long)oc0*HW + prow + 8]       = c[nt][2];
            og[(long)(oc0 + 1)*HW + prow + 8] = c[nt][3];
            sacc[nt][0] += c[nt][0] + c[nt][2];
            sacc[nt][1] += c[nt][1] + c[nt][3];
            qacc[nt][0] += c[nt][0]*c[nt][0] + c[nt][2]*c[nt][2];
            qacc[nt][1] += c[nt][1]*c[nt][1] + c[nt][3]*c[nt][3];
        }
        __syncthreads();
    }

#pragma unroll
    for (int nt = 0; nt < 2; nt++)
#pragma unroll
        for (int j = 0; j < 2; j++) {
            int oc = nhalf*16 + nt*8 + 2*(lane & 3) + j;
            atomicAdd(&s_stats[oc], sacc[nt][j]);
            atomicAdd(&s_stats[32 + oc], qacc[nt][j]);
        }
    __syncthreads();
    if (tid < 32) {
        atomicAdd(&o_sum[g*32 + tid], (double)s_stats[tid]);
        atomicAdd(&o_sq[g*32 + tid], (double)s_stats[32 + tid]);
    }
}

// ---- FFMA2 conv3x3 (e1 only) ----
template<int CIN, int SPLIT>
__global__ void __launch_bounds__(256, 2)
conv2(const float* __restrict__ in, const float* __restrict__ in2,
      const float* __restrict__ w0_, const float* __restrict__ w1_,
      const float* __restrict__ w2_, const float* __restrict__ w3_,
      float* __restrict__ out, long outStrideZ,
      double* __restrict__ o_sum, double* __restrict__ o_sq)
{
    constexpr int NCH = CIN / ICB;
    constexpr int NIN = ICB*18*66;
    constexpr int NWT = ICB*9*16;
    constexpr int NTOT = NIN + NWT;

    const int z = blockIdx.z;
    const int gate = z >> 1;
    const int ocbase = (z & 1) * 16;
    const float* wt = (gate == 0) ? w0_ : (gate == 1) ? w1_ : (gate == 2) ? w2_ : w3_;
    out   += (long)gate * outStrideZ;
    o_sum += gate*32 + ocbase;
    o_sq  += gate*32 + ocbase;

    __shared__ float s_in[2][ICB][18][68];
    __shared__ float s_w[2][ICB][9][16];
    __shared__ float s_red[8][16][2];

    const int tid = threadIdx.x;
    const int tx = tid & 15, ty = tid >> 4;
    const int x0 = blockIdx.x*64 + tx*4;
    const int oy = blockIdx.y*16 + ty;
    const int gx0 = blockIdx.x*64 - 1;
    const int gy0 = blockIdx.y*16 - 1;

    unsigned long long acc[4][8];
#pragma unroll
    for (int p = 0; p < 4; p++)
#pragma unroll
        for (int q = 0; q < 8; q++) acc[p][q] = 0ULL;

    auto issue = [&](int ch, int b) {
        int ic0 = ch * ICB;
        for (int e = tid; e < NTOT; e += 256) {
            if (e < NIN) {
                int ic = e / (18*66);
                int r  = e - ic*(18*66);
                int ly = r / 66, lx = r - ly*66;
                int gy = gy0 + ly, gx = gx0 + lx;
                bool ok = (unsigned)gy < (unsigned)H && (unsigned)gx < (unsigned)W;
                int c = ic0 + ic;
                const float* src;
                if (SPLIT && c < 32) src = ok ? &in2[(long)c*HW + gy*W + gx] : in2;
                else {
                    int cc = SPLIT ? c - 32 : c;
                    src = ok ? &in[(long)cc*HW + gy*W + gx] : in;
                }
                cp4((unsigned int)__cvta_generic_to_shared(&s_in[b][ic][ly][lx]), src, ok);
            } else {
                int r = e - NIN;
                int ic = r / 144;
                int r2 = r - ic*144;
                int k = r2 >> 4, oco = r2 & 15;
                cp4((unsigned int)__cvta_generic_to_shared(&s_w[b][ic][k][oco]),
                    &wt[((long)(ocbase + oco)*CIN + ic0 + ic)*9 + k], true);
            }
        }
        cp_commit();
    };

    issue(0, 0);

    for (int n = 0; n < NCH; n++) {
        const int b = n & 1;
        if (n + 1 < NCH) { issue(n + 1, (n + 1) & 1); cp_wait<1>(); }
        else cp_wait<0>();
        __syncthreads();

#pragma unroll
        for (int i = 0; i < ICB; i++) {
#pragma unroll
            for (int r = 0; r < 3; r++) {
                float4 va = *(const float4*)&s_in[b][i][ty + r][tx*4];
                float2 vb = *(const float2*)&s_in[b][i][ty + r][tx*4 + 4];
                unsigned long long d[6] = { dup2(va.x), dup2(va.y), dup2(va.z),
                                            dup2(va.w), dup2(vb.x), dup2(vb.y) };
#pragma unroll
                for (int c = 0; c < 3; c++) {
                    const ulonglong2* wr = (const ulonglong2*)&s_w[b][i][r*3 + c][0];
                    ulonglong2 wa = wr[0], wb2 = wr[1], wc = wr[2], wd = wr[3];
                    unsigned long long wv[8] = { wa.x, wa.y, wb2.x, wb2.y,
                                                 wc.x, wc.y, wd.x, wd.y };
#pragma unroll
                    for (int p = 0; p < 4; p++)
#pragma unroll
                        for (int q = 0; q < 8; q++)
                            fma2(acc[p][q], d[c + p], wv[q]);
                }
            }
        }
        __syncthreads();
    }

    const int lane = tid & 31, wid = tid >> 5;
    const long obase = (long)oy*W + x0;
#pragma unroll
    for (int q = 0; q < 8; q++) {
        float2 v0 = unpack2(acc[0][q]), v1 = unpack2(acc[1][q]);
        float2 v2 = unpack2(acc[2][q]), v3 = unpack2(acc[3][q]);
        float4 lo = make_float4(v0.x, v1.x, v2.x, v3.x);
        float4 hi = make_float4(v0.y, v1.y, v2.y, v3.y);
        *(float4*)(out + (long)(ocbase + 2*q    )*HW + obase) = lo;
        *(float4*)(out + (long)(ocbase + 2*q + 1)*HW + obase) = hi;

        float sl = lo.x + lo.y + lo.z + lo.w;
        float ql = lo.x*lo.x + lo.y*lo.y + lo.z*lo.z + lo.w*lo.w;
        float sh = hi.x + hi.y + hi.z + hi.w;
        float qh = hi.x*hi.x + hi.y*hi.y + hi.z*hi.z + hi.w*hi.w;
#pragma unroll
        for (int o2 = 16; o2 > 0; o2 >>= 1) {
            sl += __shfl_xor_sync(0xffffffffu, sl, o2);
            ql += __shfl_xor_sync(0xffffffffu, ql, o2);
            sh += __shfl_xor_sync(0xffffffffu, sh, o2);
            qh += __shfl_xor_sync(0xffffffffu, qh, o2);
        }
        if (lane == 0) {
            s_red[wid][2*q][0] = sl; s_red[wid][2*q][1] = ql;
            s_red[wid][2*q + 1][0] = sh; s_red[wid][2*q + 1][1] = qh;
        }
    }
    __syncthreads();
    if (tid < 16) {
        double s = 0.0, qq = 0.0;
#pragma unroll
        for (int wdx = 0; wdx < 8; wdx++) { s += (double)s_red[wdx][tid][0]; qq += (double)s_red[wdx][tid][1]; }
        atomicAdd(&o_sum[tid], s);
        atomicAdd(&o_sq[tid], qq);
    }
}

// ---- r2 conv (pad 4, 3 oc) ----
__global__ void __launch_bounds__(256, 2)
convr2(const float* __restrict__ in, const float* __restrict__ wt,
       float* __restrict__ outg, double* __restrict__ o_sum, double* __restrict__ o_sq)
{
    constexpr int NCH = 8;
    constexpr int NIN = ICB*18*66;
    __shared__ float s_in[2][ICB][18][68];
    __shared__ float s_wr[32][9][4];
    __shared__ float s_red[8][3][2];

    const int tid = threadIdx.x;
    const int tx = tid & 15, ty = tid >> 4;
    const int x0 = blockIdx.x*64;
    const int oy = blockIdx.y*16 + ty;
    const int gx0 = x0 - 4, gy0 = blockIdx.y*16 - 4;

    unsigned long long acc[2][3];
#pragma unroll
    for (int p = 0; p < 2; p++)
#pragma unroll
        for (int q = 0; q < 3; q++) acc[p][q] = 0ULL;

    auto issue = [&](int ch, int b) {
        const int ic0 = ch * ICB;
        for (int e = tid; e < NIN; e += 256) {
            int ic = e / (18*66);
            int r = e - ic*(18*66);
            int ly = r / 66, lx = r - ly*66;
            int gy = gy0 + ly, gx = gx0 + lx;
            bool ok = (unsigned)gy < (unsigned)H && (unsigned)gx < (unsigned)W;
            const float* src = ok ? &in[(long)(ic0 + ic)*HW + gy*W + gx] : in;
            cp4((unsigned int)__cvta_generic_to_shared(&s_in[b][ic][ly][lx]), src, ok);
        }
        cp_commit();
    };

    issue(0, 0);
    for (int e = tid; e < 32*9*3; e += 256) {
        int ic = e / 27, r = e - ic*27, k = r / 3, oc = r - k*3;
        s_wr[ic][k][oc] = wt[((long)oc*32 + ic)*9 + k];
    }

    for (int n = 0; n < NCH; n++) {
        const int b = n & 1;
        if (n + 1 < NCH) { issue(n + 1, (n + 1) & 1); cp_wait<1>(); }
        else cp_wait<0>();
        __syncthreads();
#pragma unroll
        for (int i = 0; i < ICB; i++) {
            const float* wbase = &s_wr[n*ICB + i][0][0];
#pragma unroll
            for (int r = 0; r < 3; r++) {
                const float* ip = &s_in[b][i][ty + r][tx*4];
                float4 va = *(const float4*)ip;
                float2 vb = *(const float2*)(ip + 4);
                unsigned long long q01 = pk2(va.x, va.y), q12 = pk2(va.y, va.z);
                unsigned long long q23 = pk2(va.z, va.w), q34 = pk2(va.w, vb.x);
                unsigned long long q45 = pk2(vb.x, vb.y);
                unsigned long long pr[3][2] = { {q01, q23}, {q12, q34}, {q23, q45} };
#pragma unroll
                for (int c = 0; c < 3; c++) {
                    float4 w4 = *(const float4*)(wbase + (r*3 + c)*4);
                    unsigned long long w0 = dup2(w4.x), w1 = dup2(w4.y), w2 = dup2(w4.z);
                    fma2(acc[0][0], pr[c][0], w0); fma2(acc[1][0], pr[c][1], w0);
                    fma2(acc[0][1], pr[c][0], w1); fma2(acc[1][1], pr[c][1], w1);
                    fma2(acc[0][2], pr[c][0], w2); fma2(acc[1][2], pr[c][1], w2);
                }
            }
        }
        __syncthreads();
    }

    const int lane = tid & 31, wid = tid >> 5;
#pragma unroll
    for (int oc = 0; oc < 3; oc++) {
        float2 u0 = unpack2(acc[0][oc]), u1 = unpack2(acc[1][oc]);
        float v[4] = { u0.x, u0.y, u1.x, u1.y };
        float s = 0.f, q = 0.f;
#pragma unroll
        for (int j = 0; j < 4; j++) {
            int ox = x0 + tx*4 + j;
            bool ok = (ox < OD2) && (oy < OD2);
            float t = ok ? v[j] : 0.f;
            if (ok) outg[(long)oc*S2 + (long)oy*OD2 + ox] = t;
            s += t; q += t*t;
        }
#pragma unroll
        for (int o2 = 16; o2 > 0; o2 >>= 1) {
            s += __shfl_xor_sync(0xffffffffu, s, o2);
            q += __shfl_xor_sync(0xffffffffu, q, o2);
        }
        if (lane == 0) { s_red[wid][oc][0] = s; s_red[wid][oc][1] = q; }
    }
    __syncthreads();
    if (tid < 3) {
        double s = 0.0, qq = 0.0;
#pragma unroll
        for (int wdx = 0; wdx < 8; wdx++) { s += (double)s_red[wdx][tid][0]; qq += (double)s_red[wdx][tid][1]; }
        atomicAdd(&o_sum[tid], s);
        atomicAdd(&o_sq[tid], qq);
    }
}

// ---- LSTM elementwise ----
__device__ __forceinline__ float fsig(float x) { return __fdividef(1.f, 1.f + __expf(-x)); }
__device__ __forceinline__ float ftanh(float x) {
    float e = __expf(-2.f*x); return __fdividef(1.f - e, 1.f + e);
}
__global__ void lstm_elem(const float* __restrict__ prev_c, float* __restrict__ out)
{
    long i4 = (long)blockIdx.x*256 + threadIdx.x;
    if (i4 >= CHW/4) return;
    int c = (int)(i4 >> 16);
    float mf = g_mean[64 + c], rf = g_rs[64 + c];
    float mi = g_mean[96 + c], ri = g_rs[96 + c];
    float mc = g_mean[128 + c], rc = g_rs[128 + c];
    float mo = g_mean[160 + c], ro = g_rs[160 + c];
    float4 gf = ((const float4*)g_gates)[i4];
    float4 gi = ((const float4*)(g_gates + CHW))[i4];
    float4 gc = ((const float4*)(g_gates + 2L*CHW))[i4];
    float4 go = ((const float4*)(g_gates + 3L*CHW))[i4];
    float4 pc = ((const float4*)prev_c)[i4];
    float4 ncv, nhv;
#define LSTM1(X) { \
        float f = fsig((gf.X - mf)*rf), it = fsig((gi.X - mi)*ri); \
        float ct = ftanh((gc.X - mc)*rc), ot = fsig((go.X - mo)*ro); \
        ncv.X = pc.X*f + it*ct; nhv.X = ftanh(ncv.X)*ot; }
    LSTM1(x) LSTM1(y) LSTM1(z) LSTM1(w)
#undef LSTM1
    ((float4*)out)[i4] = ncv;
    ((float4*)(out + CHW))[i4] = nhv;
}

// ---- gather ----
__global__ void gather_k(const int* __restrict__ coords,
                         const float* __restrict__ w_oil, const float* __restrict__ b_oil,
                         const float* __restrict__ w_wat, const float* __restrict__ b_wat,
                         const float* __restrict__ w_gas, const float* __restrict__ b_gas,
                         float* __restrict__ out)
{
    int i = threadIdx.x;
    if (i >= 256) return;
    int row = coords[2*i] + 3, col = coords[2*i + 1] + 3;
    float wv[3] = { w_oil[0], w_wat[0], w_gas[0] };
    float bv[3] = { b_oil[0], b_wat[0], b_gas[0] };
#pragma unroll
    for (int ch = 0; ch < 3; ch++) {
        float v = (g_r2[(long)ch*S2 + (long)row*OD2 + col] - g_mean[224 + ch]) * g_rs[224 + ch];
        out[2L*CHW + (long)i*3 + ch] = v * wv[ch] + bv[ch];
    }
}

// ---- launch ----
extern "C" void kernel_launch(void* const* d_in, const int* in_sizes, int n_in,
                              void* d_out, int out_size)
{
    const float* x      = (const float*)d_in[0];
    const float* prev_c = (const float*)d_in[1];
    const float* prev_h = (const float*)d_in[2];
    const int*   holes  = (const int*)  d_in[3];
    const float* w_e1 = (const float*)d_in[4];
    const float* w_e2 = (const float*)d_in[5];
    const float* w_f  = (const float*)d_in[6];
    const float* w_i  = (const float*)d_in[7];
    const float* w_c  = (const float*)d_in[8];
    const float* w_o  = (const float*)d_in[9];
    const float* w_r1 = (const float*)d_in[10];
    const float* w_r2 = (const float*)d_in[11];
    const float* w_oil = (const float*)d_in[12];
    const float* b_oil = (const float*)d_in[13];
    const float* w_wat = (const float*)d_in[14];
    const float* b_wat = (const float*)d_in[15];
    const float* w_gas = (const float*)d_in[16];
    const float* b_gas = (const float*)d_in[17];
    float* out = (float*)d_out;

    float *t1, *t1n, *t2, *gates, *r1, *r2;
    unsigned short *xa64, *xa32, *wp64, *wp32;
    double *sum, *sq;
    cudaGetSymbolAddress((void**)&t1, g_t1);
    cudaGetSymbolAddress((void**)&t1n, g_t1n);
    cudaGetSymbolAddress((void**)&t2, g_t2);
    cudaGetSymbolAddress((void**)&gates, g_gates);
    cudaGetSymbolAddress((void**)&r1, g_r1);
    cudaGetSymbolAddress((void**)&r2, g_r2);
    cudaGetSymbolAddress((void**)&xa64, g_xa64);
    cudaGetSymbolAddress((void**)&xa32, g_xa32);
    cudaGetSymbolAddress((void**)&wp64, g_wp64);
    cudaGetSymbolAddress((void**)&wp32, g_wp32);
    cudaGetSymbolAddress((void**)&sum, g_sum);
    cudaGetSymbolAddress((void**)&sq, g_sq);

    const double invHW = 1.0 / (double)HW;
    const double invS2 = 1.0 / (double)S2;
    const int SMB64 = 18*(32*272) + 4*(66*272);   // 156672 + 71808 = 228480
    const int SMB32 = 18*(32*144) + 4*(66*144);   // 82944 + 38016 = 120960
    cudaFuncSetAttribute(tcconv<64>, cudaFuncAttributeMaxDynamicSharedMemorySize, SMB64);
    cudaFuncSetAttribute(tcconv<32>, cudaFuncAttributeMaxDynamicSharedMemorySize, SMB32);

    dim3 blk(256);
    dim3 gw2(8, 32, 2);
    dim3 gr2(9, 33, 1);
    dim3 gtc64(8, 16, 4);
    dim3 gtc32(8, 16, 1);
    dim3 gpk(16, 512);
    const int NB4 = (CHW/4 + 255) / 256;

    zero_stats<<<1, 256>>>();
    wpack64<<<dim3(9, 2, 4), 128>>>(w_f, w_i, w_c, w_o, wp64);
    wpack32<<<dim3(9, 2, 2), 128>>>(w_e2, w_r1, wp32);
    // gates concat ch 0..31 = prev_h (raw)
    packT<0, 0, 256, 64><<<gpk, 256>>>(prev_h, xa64, 0, 0);

    // e1 (FFMA2) -> t1, stats stage 0
    conv2<4, 0><<<gw2, blk>>>(x, nullptr, w_e1, w_e1, w_e1, w_e1, t1, 0, sum + 0, sq + 0);
    finalize_stats<<<1, 32>>>(0, 32, invHW);
    // e2 input = relu(bn(t1)) packed px-major
    packT<1, 1, 128, 32><<<gpk, 256>>>(t1, xa32, 0, 0);

    // e2 (tensor) -> t2, stats stage 1
    tcconv<32><<<gtc32, blk, SMB32>>>(xa32, wp32, t2, 0, sum + 32, sq + 32);
    finalize_stats<<<1, 32>>>(1, 32, invHW);
    // gates concat ch 32..63 = bn(t2)
    packT<1, 0, 256, 64><<<gpk, 256>>>(t2, xa64, 32, 1);

    // gates (tensor), stats stages 2..5
    tcconv<64><<<gtc64, blk, SMB64>>>(xa64, wp64, gates, (long)CHW, sum + 64, sq + 64);
    finalize_stats<<<4, 32>>>(2, 32, invHW);

    lstm_elem<<<NB4, 256>>>(prev_c, out);

    // r1 input = next_h (raw) packed
    packT<0, 0, 128, 32><<<gpk, 256>>>(out + CHW, xa32, 0, 0);
    // r1 (tensor) -> r1, stats stage 6
    tcconv<32><<<gtc32, blk, SMB32>>>(xa32, wp32 + (long)9*2*32*72, r1, 0, sum + 192, sq + 192);
    finalize_stats<<<1, 32>>>(6, 32, invHW);
    normalize<1><<<NB4, 256>>>(r1, t1n, 6);

    convr2<<<gr2, blk>>>(t1n, w_r2, r2, sum + 224, sq + 224);
    finalize_stats<<<1, 32>>>(7, 3, invS2);

    gather_k<<<1, 256>>>(holes, w_oil, b_oil, w_wat, b_wat, w_gas, b_gas, out);
}